// round 8
// baseline (speedup 1.0000x reference)
#include <cuda_runtime.h>
#include <cstdint>

#define VOCAB 32000
#define BOS_ID 1
#define BSZ 8
#define SEQLEN 2048

#define FILL_BLOCKS 64000            // each covers 2048 float4 = 32KB
#define TOTAL_BLOCKS (FILL_BLOCKS + BSZ)

// Scratch: per-row histogram in gmem (keeps fill blocks at zero smem).
__device__ int g_counts[BSZ][VOCAB];
__device__ int g_pred[BSZ];
// g_ready: #hist blocks done. g_consumed: #fill blocks that have READ the flag.
// The last consumer resets both -> every graph replay starts from clean state.
__device__ unsigned g_ready = 0;
__device__ unsigned g_consumed = 0;

__global__ void __launch_bounds__(256) fused_kernel(const int* __restrict__ ids,
                                                    float* __restrict__ out) {
    const int bid = blockIdx.x;
    const int t = threadIdx.x;

    if (bid < BSZ) {
        // ---------------- HIST PATH (blocks 0..7, wave 1) -------------------
        const int b = bid;
        __shared__ int warp_best[8];

        // 1. Zero this row's histogram (8000 int4 = 128KB).
        int4* c4 = (int4*)g_counts[b];
        for (int i = t; i < VOCAB / 4; i += 256) c4[i] = make_int4(0, 0, 0, 0);
        __threadfence();
        __syncthreads();

        // 2. Accumulate. valid <=> v != 0 && v != 1 <=> v > 1.
        const int* row = ids + b * SEQLEN;
        #pragma unroll
        for (int i = t; i < SEQLEN; i += 256) {
            int vtok = row[i];
            if (vtok > BOS_ID) atomicAdd(&g_counts[b][vtok], 1);
        }
        __threadfence();
        __syncthreads();

        // 3. Argmax. Packed key: (count << 15) | (0x7FFF - v).
        //    Higher count wins; equal count -> lower v (argmax tie rule).
        //    count <= 2048 (12b), v < 32000 (15b) -> packed < 2^27.
        //    __ldcg: atomics updated L2; bypass possibly-stale L1.
        int best = 0;
        for (int i = t; i < VOCAB / 4; i += 256) {
            int4 c = __ldcg(&c4[i]);
            int vb = 0x7FFF - 4 * i;
            best = max(best, (c.x << 15) | vb);
            best = max(best, (c.y << 15) | (vb - 1));
            best = max(best, (c.z << 15) | (vb - 2));
            best = max(best, (c.w << 15) | (vb - 3));
        }
        best = __reduce_max_sync(0xFFFFFFFFu, best);
        if ((t & 31) == 0) warp_best[t >> 5] = best;
        __syncthreads();
        if (t == 0) {
            int wb = warp_best[0];
            #pragma unroll
            for (int w = 1; w < 8; w++) wb = max(wb, warp_best[w]);
            int cnt = wb >> 15;
            g_pred[b] = (cnt > 0) ? (0x7FFF - (wb & 0x7FFF)) : BOS_ID;
            __threadfence();                  // publish pred before the flag
            atomicAdd(&g_ready, 1u);
        }
        return;
    }

    // ---------------- FILL PATH: wait (wave 1 only, ~2us), then stream ------
    {
        volatile unsigned* gr = &g_ready;
        if (*gr < (unsigned)BSZ) {
            while (*gr < (unsigned)BSZ) __nanosleep(32);
        }
    }
    __threadfence();   // leading fence, no stores in flight -> cheap, no drain

    const long long f = (long long)(bid - BSZ);       // fill-block index
    // Block f covers global float4 [f*2048, (f+1)*2048). Each 32KB region lies
    // entirely inside one batch (PER_B = 16,384,000 is a multiple of 2048).
    const long long PER_B = (long long)SEQLEN * (VOCAB / 4);
    const long long base = f * 2048;
    const int b = (int)(base / PER_B);
    const int pred = __ldcg(&g_pred[b]);

    // Signal "flag+pred consumed" BEFORE issuing bulk stores (no drain coupling).
    if (t == 0) {
        unsigned old = atomicAdd(&g_consumed, 1u);
        if (old == (unsigned)(FILL_BLOCKS - 1)) {     // last consumer: reset
            g_ready = 0;
            g_consumed = 0;
        }
    }

    // 8 coalesced STG.128 per thread; per-store pred-compare merged in.
    float4* out4 = (float4*)out;
    #pragma unroll
    for (int j = 0; j < 8; j++) {
        const long long gidx = base + j * 256 + t;    // global float4 index
        const int r = (int)(gidx % (VOCAB / 4));      // float4 idx in vocab row
        float4 val = make_float4(-6.0f, -6.0f, -6.0f, -6.0f);
        const int vb = r * 4;
        if (pred >= vb && pred < vb + 4) {
            reinterpret_cast<float*>(&val)[pred - vb] = 6.0f;
        }
        out4[gidx] = val;
    }
}

// ---------------------------------------------------------------------------
extern "C" void kernel_launch(void* const* d_in, const int* in_sizes, int n_in,
                              void* d_out, int out_size) {
    (void)in_sizes; (void)n_in; (void)out_size;
    const int* ids = (const int*)d_in[0];
    fused_kernel<<<TOTAL_BLOCKS, 256>>>(ids, (float*)d_out);
}

// round 9
// speedup vs baseline: 1.3913x; 1.3913x over previous
#include <cuda_runtime.h>
#include <cstdint>

#define VOCAB 32000
#define BOS_ID 1
#define BSZ 8
#define SEQLEN 2048

#define ROW4 (VOCAB / 4)             // 8000 float4 per (b,s) row
#define FILL_BLOCKS 64000            // each covers 2048 float4 = 32KB
#define BLOCKS_PER_B 8000            // fill blocks per batch row
#define TOTAL_BLOCKS (FILL_BLOCKS + BSZ)

// Scratch: per-row histogram in gmem (keeps fill blocks at zero smem cost).
__device__ int g_counts[BSZ][VOCAB];
__device__ int g_pred[BSZ];
// g_ready: #hist blocks done (release-published). g_consumed: #fill blocks that
// consumed the flag. Last consumer resets both -> clean state for every replay.
__device__ unsigned g_ready = 0;
__device__ unsigned g_consumed = 0;

__global__ void __launch_bounds__(256) fused_kernel(const int* __restrict__ ids,
                                                    float* __restrict__ out) {
    const int bid = blockIdx.x;
    const int t = threadIdx.x;

    if (bid < BSZ) {
        // ---------------- HIST PATH (blocks 0..7, wave 1) -------------------
        const int b = bid;
        __shared__ int warp_best[8];

        // 1. Zero this row's histogram (8000 int4 = 128KB, gmem).
        int4* c4 = (int4*)g_counts[b];
        for (int i = t; i < VOCAB / 4; i += 256) c4[i] = make_int4(0, 0, 0, 0);
        __threadfence();
        __syncthreads();

        // 2. Accumulate. valid <=> v != 0 && v != 1 <=> v > 1.
        const int* row = ids + b * SEQLEN;
        #pragma unroll
        for (int i = t; i < SEQLEN; i += 256) {
            int vtok = row[i];
            if (vtok > BOS_ID) atomicAdd(&g_counts[b][vtok], 1);
        }
        __threadfence();
        __syncthreads();

        // 3. Argmax. Packed key: (count << 15) | (0x7FFF - v).
        //    Higher count wins; equal count -> lower v (argmax tie rule).
        //    count <= 2048 (12b), v < 32000 (15b) -> packed < 2^27.
        //    __ldcg: atomics updated L2; bypass possibly-stale L1.
        int best = 0;
        for (int i = t; i < VOCAB / 4; i += 256) {
            int4 c = __ldcg(&c4[i]);
            int vb = 0x7FFF - 4 * i;
            best = max(best, (c.x << 15) | vb);
            best = max(best, (c.y << 15) | (vb - 1));
            best = max(best, (c.z << 15) | (vb - 2));
            best = max(best, (c.w << 15) | (vb - 3));
        }
        best = __reduce_max_sync(0xFFFFFFFFu, best);
        if ((t & 31) == 0) warp_best[t >> 5] = best;
        __syncthreads();
        if (t == 0) {
            int wb = warp_best[0];
            #pragma unroll
            for (int w = 1; w < 8; w++) wb = max(wb, warp_best[w]);
            int cnt = wb >> 15;
            g_pred[b] = (cnt > 0) ? (0x7FFF - (wb & 0x7FFF)) : BOS_ID;
            __threadfence();                  // release: publish pred, then flag
            atomicAdd(&g_ready, 1u);
        }
        return;
    }

    // ---------------- FILL PATH: t0-only wait, then fence-free stream -------
    __shared__ int s_pred;
    const int f = bid - BSZ;                  // fill-block index, < 64000
    const int b = f / BLOCKS_PER_B;           // 32-bit magic div

    if (t == 0) {
        // Acquire-spin on the flag: one load per block after wave 1.
        unsigned r;
        #if __CUDA_ARCH__ >= 700
        asm volatile("ld.acquire.gpu.global.u32 %0, [%1];"
                     : "=r"(r) : "l"(&g_ready) : "memory");
        while (r < (unsigned)BSZ) {
            __nanosleep(32);
            asm volatile("ld.acquire.gpu.global.u32 %0, [%1];"
                         : "=r"(r) : "l"(&g_ready) : "memory");
        }
        #endif
        s_pred = __ldcg(&g_pred[b]);
        // Consume-count for the end-of-launch reset (single t0 atomic/block).
        unsigned old = atomicAdd(&g_consumed, 1u);
        if (old == (unsigned)(FILL_BLOCKS - 1)) {   // last consumer: reset
            g_ready = 0;
            g_consumed = 0;
        }
    }
    __syncthreads();
    const int pred = s_pred;
    const int pc4 = pred >> 2;                // float4 column holding pred
    const int plane = pred & 3;

    // r0 = (f*2048) mod 8000, all 32-bit: ((f mod 8000) * 2048) mod 8000.
    const int r0 = ((f % BLOCKS_PER_B) * 2048) % ROW4;

    // 8 coalesced STG.128 per thread; per-store cost = 1 add + 1 cond-sub + 1 cmp.
    float4* p = (float4*)out + (long long)f * 2048 + t;
    #pragma unroll
    for (int j = 0; j < 8; j++) {
        int s = r0 + j * 256 + t;             // < 10047
        if (s >= ROW4) s -= ROW4;
        float4 val = make_float4(-6.0f, -6.0f, -6.0f, -6.0f);
        if (s == pc4) reinterpret_cast<float*>(&val)[plane] = 6.0f;
        p[j * 256] = val;
    }
}

// ---------------------------------------------------------------------------
extern "C" void kernel_launch(void* const* d_in, const int* in_sizes, int n_in,
                              void* d_out, int out_size) {
    (void)in_sizes; (void)n_in; (void)out_size;
    const int* ids = (const int*)d_in[0];
    fused_kernel<<<TOTAL_BLOCKS, 256>>>(ids, (float*)d_out);
}

// round 10
// speedup vs baseline: 1.4440x; 1.0379x over previous
#include <cuda_runtime.h>
#include <cstdint>

#define VOCAB 32000
#define BOS_ID 1
#define BSZ 8
#define SEQLEN 2048

// ---------------------------------------------------------------------------
// Kernel A: pure -6.0f broadcast. Zero dependencies, zero index math beyond
// the base offset, zero epilogue. 8 coalesced STG.128 per thread.
// 131,072,000 float4 / 2048 per block = 64000 blocks.
// Triggers PDL completion at entry so kernel B can run concurrently.
// ---------------------------------------------------------------------------
__global__ void __launch_bounds__(256) fill_kernel(float4* __restrict__ out) {
    cudaTriggerProgrammaticLaunchCompletion();
    const float4 v = make_float4(-6.0f, -6.0f, -6.0f, -6.0f);
    float4* p = out + (long long)blockIdx.x * 2048 + threadIdx.x;
    #pragma unroll
    for (int j = 0; j < 8; j++) {
        p[j * 256] = v;
    }
}

// ---------------------------------------------------------------------------
// Kernel B (PDL): per-row histogram + argmax — runs CONCURRENTLY with the
// fill (no dependence) — then waits for the fill grid to complete, then
// patches +6.0f at (b, s, pred) for all s (2048 scattered stores per row).
// One block per batch row; dynamic smem = VOCAB ints (128000 B, opt-in).
// ---------------------------------------------------------------------------
__global__ void __launch_bounds__(1024) hist_patch_kernel(const int* __restrict__ ids,
                                                          float* __restrict__ out) {
    extern __shared__ int counts[];
    __shared__ int warp_best[32];

    const int b = blockIdx.x;
    const int t = threadIdx.x;

    int4* c4 = (int4*)counts;               // VOCAB/4 = 8000 int4
    #pragma unroll
    for (int i = t; i < VOCAB / 4; i += 1024) c4[i] = make_int4(0, 0, 0, 0);
    __syncthreads();

    const int* row = ids + b * SEQLEN;
    #pragma unroll
    for (int i = t; i < SEQLEN; i += 1024) {
        int v = row[i];
        if (v > BOS_ID) atomicAdd(&counts[v], 1);  // valid <=> v!=0 && v!=1 <=> v>1
    }
    __syncthreads();

    // Packed key: (count << 15) | (0x7FFF - v).
    // Higher count wins; equal count -> lower v wins (argmax tie rule).
    // count <= 2048 (12 bits), v < 32000 (15 bits) -> packed < 2^27.
    int best = 0;
    #pragma unroll
    for (int i = t; i < VOCAB / 4; i += 1024) {
        int4 c = c4[i];
        int vb = 0x7FFF - 4 * i;
        best = max(best, (c.x << 15) | vb);
        best = max(best, (c.y << 15) | (vb - 1));
        best = max(best, (c.z << 15) | (vb - 2));
        best = max(best, (c.w << 15) | (vb - 3));
    }
    best = __reduce_max_sync(0xFFFFFFFFu, best);
    if ((t & 31) == 0) warp_best[t >> 5] = best;
    __syncthreads();

    __shared__ int s_pred;
    if (t < 32) {
        int wb = __reduce_max_sync(0xFFFFFFFFu, warp_best[t]);
        if (t == 0) {
            int cnt = wb >> 15;
            s_pred = (cnt > 0) ? (0x7FFF - (wb & 0x7FFF)) : BOS_ID;
        }
    }

    // Wait for the fill grid to fully complete (orders our patch stores after
    // all of A's -6 stores). All hist work above overlapped with the fill.
    cudaGridDependencySynchronize();
    __syncthreads();
    const int pred = s_pred;

    // Patch: out[b][s][pred] = +6 for every s. 2048 scattered 4B stores/block.
    float* base = out + (long long)b * SEQLEN * VOCAB + pred;
    #pragma unroll
    for (int s = t; s < SEQLEN; s += 1024) {
        base[(long long)s * VOCAB] = 6.0f;
    }
}

// ---------------------------------------------------------------------------
extern "C" void kernel_launch(void* const* d_in, const int* in_sizes, int n_in,
                              void* d_out, int out_size) {
    (void)in_sizes; (void)n_in; (void)out_size;
    const int* ids = (const int*)d_in[0];

    const int smem_bytes = VOCAB * (int)sizeof(int);  // 128000 bytes
    cudaFuncSetAttribute(hist_patch_kernel,
                         cudaFuncAttributeMaxDynamicSharedMemorySize, smem_bytes);

    // A: dependency-free fill, starts storing immediately.
    fill_kernel<<<64000, 256>>>((float4*)d_out);

    // B: PDL launch — hist overlaps with A; griddepsync gates only the patch.
    cudaLaunchConfig_t cfg = {};
    cfg.gridDim = dim3(BSZ);
    cfg.blockDim = dim3(1024);
    cfg.dynamicSmemBytes = smem_bytes;
    cfg.stream = 0;
    cudaLaunchAttribute attrs[1];
    attrs[0].id = cudaLaunchAttributeProgrammaticStreamSerialization;
    attrs[0].val.programmaticStreamSerializationAllowed = 1;
    cfg.attrs = attrs;
    cfg.numAttrs = 1;
    cudaLaunchKernelEx(&cfg, hist_patch_kernel, ids, (float*)d_out);
}